// round 9
// baseline (speedup 1.0000x reference)
#include <cuda_runtime.h>
#include <cuda_bf16.h>
#include <cstdint>

#define BB   2
#define SS   2048
#define HH   16
#define DK   64
#define DM   1024
#define MM   (BB*SS)
#define OUT_ELEMS  (4194304)

// Scratch (allocation-free rule: device globals)
__device__ __nv_bfloat16 g_qh[BB*HH*SS*DK];   // q hi, [bh][s][d]
__device__ __nv_bfloat16 g_ql[BB*HH*SS*DK];   // q lo
__device__ __nv_bfloat16 g_kh[BB*HH*SS*DK];   // k hi
__device__ __nv_bfloat16 g_kl[BB*HH*SS*DK];   // k lo
__device__ float g_v [BB*HH*DK*SS];           // v TRANSPOSED fp32: [bh][d][s]
__device__ float g_ao[MM*DM];                 // attn_out, (b,s,h,d) flat

// ---------------------------------------------------------------------------
__device__ __forceinline__ void mma16(float* c, const uint32_t* a, const uint32_t* b) {
    asm volatile("mma.sync.aligned.m16n8k16.row.col.f32.bf16.bf16.f32 "
        "{%0,%1,%2,%3},{%4,%5,%6,%7},{%8,%9},{%0,%1,%2,%3};"
        : "+f"(c[0]), "+f"(c[1]), "+f"(c[2]), "+f"(c[3])
        : "r"(a[0]), "r"(a[1]), "r"(a[2]), "r"(a[3]), "r"(b[0]), "r"(b[1]));
}

__device__ __forceinline__ void ldsm4(uint32_t* r, uint32_t addr) {
    asm volatile("ldmatrix.sync.aligned.m8n8.x4.shared.b16 {%0,%1,%2,%3}, [%4];"
        : "=r"(r[0]), "=r"(r[1]), "=r"(r[2]), "=r"(r[3]) : "r"(addr));
}

__device__ __forceinline__ uint32_t smem_u32(const void* p) {
    return (uint32_t)__cvta_generic_to_shared(p);
}

// convert 4 floats -> 4 hi bf16 (8B) + 4 lo bf16 (8B)
__device__ __forceinline__ void cvt_hilo(const float4 v, uint2* ph, uint2* pl) {
    __nv_bfloat162 h0 = __floats2bfloat162_rn(v.x, v.y);
    __nv_bfloat162 h1 = __floats2bfloat162_rn(v.z, v.w);
    __nv_bfloat162 l0 = __floats2bfloat162_rn(v.x - __bfloat162float(h0.x),
                                              v.y - __bfloat162float(h0.y));
    __nv_bfloat162 l1 = __floats2bfloat162_rn(v.z - __bfloat162float(h1.x),
                                              v.w - __bfloat162float(h1.y));
    *ph = make_uint2(*(uint32_t*)&h0, *(uint32_t*)&h1);
    *pl = make_uint2(*(uint32_t*)&l0, *(uint32_t*)&l1);
}

// pack 2 floats -> hi bf16x2, and residual lo bf16x2
__device__ __forceinline__ uint32_t pack_hilo(float x, float y, uint32_t* lo) {
    __nv_bfloat162 h = __floats2bfloat162_rn(x, y);
    __nv_bfloat162 l = __floats2bfloat162_rn(x - __bfloat162float(h.x),
                                             y - __bfloat162float(h.y));
    *lo = *(uint32_t*)&l;
    return *(uint32_t*)&h;
}

// ===========================================================================
// fp32-input bf16x3 NT GEMM (proven R7). C = scale*(A @ B^T)(+bias).
// MODE: 0 row-major fp32 C; 1 bf16 hi/lo scatter [b,h,s,d]; 2 fp32 scatter [b,h,d,s]
// ===========================================================================
template<int MODE>
__global__ void __launch_bounds__(256, 2) gemm_f32(
    const float* __restrict__ A, const float* __restrict__ B,
    const float* __restrict__ bias, float* __restrict__ C,
    __nv_bfloat16* __restrict__ Ch, __nv_bfloat16* __restrict__ Cl,
    int N, int K, float scale)
{
    constexpr int BK = 32, SK = 40;

    __shared__ __nv_bfloat16 Ah[128 * SK], Al[128 * SK];
    __shared__ __nv_bfloat16 Bh[64 * SK],  Bl[64 * SK];

    const int tid = threadIdx.x, w = tid >> 5, lane = tid & 31;
    const int g = lane >> 2, t = lane & 3;
    const int m0 = blockIdx.y * 128, n0 = blockIdx.x * 64;
    const int wm0 = (w & 3) * 32, wn0 = (w >> 2) * 32;

    const uint32_t ah_b = smem_u32(Ah), al_b = smem_u32(Al);
    const uint32_t bh_b = smem_u32(Bh), bl_b = smem_u32(Bl);

    float acc[2][4][4];
    #pragma unroll
    for (int i = 0; i < 2; i++)
        #pragma unroll
        for (int j = 0; j < 4; j++)
            #pragma unroll
            for (int e = 0; e < 4; e++) acc[i][j][e] = 0.f;

    float4 ra[4], rb[2];
    #pragma unroll
    for (int i = 0; i < 4; i++) {
        int idx = tid + i * 256;
        ra[i] = *(const float4*)(A + (long long)(m0 + (idx >> 3)) * K + (idx & 7) * 4);
    }
    #pragma unroll
    for (int i = 0; i < 2; i++) {
        int idx = tid + i * 256;
        rb[i] = *(const float4*)(B + (long long)(n0 + (idx >> 3)) * K + (idx & 7) * 4);
    }

    for (int k0 = 0; k0 < K; k0 += BK) {
        __syncthreads();
        #pragma unroll
        for (int i = 0; i < 4; i++) {
            int idx = tid + i * 256, r = idx >> 3, c = (idx & 7) * 4;
            cvt_hilo(ra[i], (uint2*)&Ah[r * SK + c], (uint2*)&Al[r * SK + c]);
        }
        #pragma unroll
        for (int i = 0; i < 2; i++) {
            int idx = tid + i * 256, r = idx >> 3, c = (idx & 7) * 4;
            cvt_hilo(rb[i], (uint2*)&Bh[r * SK + c], (uint2*)&Bl[r * SK + c]);
        }
        __syncthreads();

        if (k0 + BK < K) {
            #pragma unroll
            for (int i = 0; i < 4; i++) {
                int idx = tid + i * 256;
                ra[i] = *(const float4*)(A + (long long)(m0 + (idx >> 3)) * K + k0 + BK + (idx & 7) * 4);
            }
            #pragma unroll
            for (int i = 0; i < 2; i++) {
                int idx = tid + i * 256;
                rb[i] = *(const float4*)(B + (long long)(n0 + (idx >> 3)) * K + k0 + BK + (idx & 7) * 4);
            }
        }

        #pragma unroll
        for (int ks = 0; ks < 2; ks++) {
            const int arow = wm0 + (lane & 7) + ((lane >> 3) & 1) * 8;
            const int acol = ks * 16 + (lane >> 4) * 8;
            const int brow = wn0 + (lane & 7) + (lane >> 4) * 8;
            const int bcol = ((lane >> 3) & 1) * 8 + ks * 16;

            uint32_t af[2][4], afl[2][4], bf[2][4], bfl[2][4];
            #pragma unroll
            for (int f = 0; f < 2; f++) {
                uint32_t off = ((arow + f * 16) * SK + acol) * 2;
                ldsm4(af[f],  ah_b + off);
                ldsm4(afl[f], al_b + off);
            }
            #pragma unroll
            for (int p = 0; p < 2; p++) {
                uint32_t off = ((brow + p * 16) * SK + bcol) * 2;
                ldsm4(bf[p],  bh_b + off);
                ldsm4(bfl[p], bl_b + off);
            }

            #pragma unroll
            for (int mf = 0; mf < 2; mf++)
                #pragma unroll
                for (int nf = 0; nf < 4; nf++) {
                    const uint32_t* bp = &bf[nf >> 1][(nf & 1) * 2];
                    const uint32_t* lp = &bfl[nf >> 1][(nf & 1) * 2];
                    mma16(acc[mf][nf], afl[mf], bp);
                    mma16(acc[mf][nf], af[mf],  lp);
                    mma16(acc[mf][nf], af[mf],  bp);
                }
        }
    }

    #pragma unroll
    for (int mf = 0; mf < 2; mf++) {
        #pragma unroll
        for (int nf = 0; nf < 4; nf++) {
            const int gn = n0 + wn0 + nf * 8 + 2 * t;
            float b0 = 0.f, b1 = 0.f;
            if (bias) { b0 = __ldg(&bias[gn]); b1 = __ldg(&bias[gn + 1]); }
            #pragma unroll
            for (int h = 0; h < 2; h++) {
                const int gm = m0 + wm0 + mf * 16 + g + h * 8;
                float v0 = acc[mf][nf][h * 2 + 0] * scale + b0;
                float v1 = acc[mf][nf][h * 2 + 1] * scale + b1;
                if (MODE == 0) {
                    float2 p = {v0, v1};
                    *(float2*)&C[(long long)gm * N + gn] = p;
                } else if (MODE == 1) {
                    int b = gm >> 11, s = gm & (SS - 1);
                    int hh = gn >> 6, d = gn & 63;
                    long long idx = (((long long)(b * HH + hh)) * SS + s) * DK + d;
                    __nv_bfloat162 hp = __floats2bfloat162_rn(v0, v1);
                    __nv_bfloat162 lp = __floats2bfloat162_rn(v0 - __bfloat162float(hp.x),
                                                              v1 - __bfloat162float(hp.y));
                    *(uint32_t*)&Ch[idx] = *(uint32_t*)&hp;
                    *(uint32_t*)&Cl[idx] = *(uint32_t*)&lp;
                } else { // MODE 2
                    int b = gm >> 11, s = gm & (SS - 1);
                    int hh = gn >> 6, d = gn & 63;
                    C[(((long long)(b * HH + hh)) * DK + d) * SS + s] = v0;
                    C[(((long long)(b * HH + hh)) * DK + d + 1) * SS + s] = v1;
                }
            }
        }
    }
}

// ===========================================================================
// Fused attention: logits (bf16x3 mma) -> sparsemax (register strip) ->
// P write (only big traffic) -> PV (acc->A-frag transmute, bf16x3).
// CTA: 256 thr, 16 q-rows x K=2048. Warp w owns cols 16*(8*kt+w)+0..15, kt=0..15.
// ===========================================================================
__global__ void __launch_bounds__(256) fused_attn(
    const __nv_bfloat16* __restrict__ Qh, const __nv_bfloat16* __restrict__ Ql,
    const __nv_bfloat16* __restrict__ Kh, const __nv_bfloat16* __restrict__ Kl,
    const float* __restrict__ V, float* __restrict__ attn, float* __restrict__ ao)
{
    extern __shared__ char sm[];
    __shared__ float redA[16][8];
    __shared__ float redB[16][8];

    __nv_bfloat16* QHs = (__nv_bfloat16*)(sm);            // 16x72
    __nv_bfloat16* QLs = (__nv_bfloat16*)(sm + 2304);
    __nv_bfloat16* KHs = (__nv_bfloat16*)(sm + 4608);     // 128x72
    __nv_bfloat16* KLs = (__nv_bfloat16*)(sm + 23040);
    __nv_bfloat16* VHs = (__nv_bfloat16*)(sm + 4608);     // 64x136 (phase C)
    __nv_bfloat16* VLs = (__nv_bfloat16*)(sm + 22016);
    float*         Osm = (float*)(sm + 4608);             // 8x16x64 (final)

    const int tid = threadIdx.x, w = tid >> 5, lane = tid & 31;
    const int g = lane >> 2, t = lane & 3;
    const int row0 = blockIdx.x * 16;
    const int bh = blockIdx.y;

    // ---- load Q tile (16x64 hi/lo) ----
    if (tid < 128) {
        int r = tid >> 3, c = (tid & 7) * 8;
        long long src = ((long long)bh * SS + row0 + r) * DK + c;
        *(uint4*)&QHs[r * 72 + c] = *(const uint4*)&Qh[src];
        *(uint4*)&QLs[r * 72 + c] = *(const uint4*)&Ql[src];
    }
    __syncthreads();

    // ---- Q A-fragments (persist through phase A) ----
    uint32_t qh4[4][4], ql4[4][4];
    {
        int arow = (lane & 7) + ((lane >> 3) & 1) * 8;
        #pragma unroll
        for (int ks = 0; ks < 4; ks++) {
            uint32_t off = (uint32_t)(arow * 72 + ks * 16 + (lane >> 4) * 8) * 2;
            ldsm4(qh4[ks], smem_u32(QHs) + off);
            ldsm4(ql4[ks], smem_u32(QLs) + off);
        }
    }

    float acc[32][4];
    #pragma unroll
    for (int f = 0; f < 32; f++)
        #pragma unroll
        for (int e = 0; e < 4; e++) acc[f][e] = 0.f;

    // ================= Phase A: logits =================
    for (int kt = 0; kt < 16; kt++) {
        __syncthreads();
        #pragma unroll
        for (int i = 0; i < 4; i++) {
            int idx = tid + i * 256, r = idx >> 3, c = (idx & 7) * 8;
            long long src = ((long long)bh * SS + kt * 128 + r) * DK + c;
            *(uint4*)&KHs[r * 72 + c] = *(const uint4*)&Kh[src];
            *(uint4*)&KLs[r * 72 + c] = *(const uint4*)&Kl[src];
        }
        __syncthreads();

        const int brow = 16 * w + (lane & 7) + (lane >> 4) * 8;
        #pragma unroll
        for (int ks = 0; ks < 4; ks++) {
            uint32_t off = (uint32_t)(brow * 72 + ((lane >> 3) & 1) * 8 + ks * 16) * 2;
            uint32_t b4[4], bl4[4];
            ldsm4(b4,  smem_u32(KHs) + off);
            ldsm4(bl4, smem_u32(KLs) + off);
            #pragma unroll
            for (int nf = 0; nf < 2; nf++) {
                float* a = acc[kt * 2 + nf];
                mma16(a, ql4[ks], &b4[nf * 2]);
                mma16(a, qh4[ks], &bl4[nf * 2]);
                mma16(a, qh4[ks], &b4[nf * 2]);
            }
        }
    }

    // ================= sparsemax on register strip =================
    float m0 = -1e30f, m1 = -1e30f;
    #pragma unroll
    for (int f = 0; f < 32; f++) {
        #pragma unroll
        for (int e = 0; e < 4; e++) acc[f][e] *= 0.125f;
        m0 = fmaxf(m0, fmaxf(acc[f][0], acc[f][1]));
        m1 = fmaxf(m1, fmaxf(acc[f][2], acc[f][3]));
    }
    m0 = fmaxf(m0, __shfl_xor_sync(0xffffffffu, m0, 1));
    m0 = fmaxf(m0, __shfl_xor_sync(0xffffffffu, m0, 2));
    m1 = fmaxf(m1, __shfl_xor_sync(0xffffffffu, m1, 1));
    m1 = fmaxf(m1, __shfl_xor_sync(0xffffffffu, m1, 2));
    if (t == 0) { redA[g][w] = m0; redA[g + 8][w] = m1; }
    __syncthreads();
    float mx0 = -1e30f, mx1 = -1e30f;
    #pragma unroll
    for (int wi = 0; wi < 8; wi++) {
        mx0 = fmaxf(mx0, redA[g][wi]);
        mx1 = fmaxf(mx1, redA[g + 8][wi]);
    }
    __syncthreads();

    float lo0 = mx0 - 1.f, hi0 = mx0, lo1 = mx1 - 1.f, hi1 = mx1;
    for (int it = 0; it < 12; it++) {
        float mid0 = 0.5f * (lo0 + hi0), mid1 = 0.5f * (lo1 + hi1);
        float s0 = 0.f, s1 = 0.f;
        #pragma unroll
        for (int f = 0; f < 32; f++) {
            s0 += fmaxf(acc[f][0] - mid0, 0.f) + fmaxf(acc[f][1] - mid0, 0.f);
            s1 += fmaxf(acc[f][2] - mid1, 0.f) + fmaxf(acc[f][3] - mid1, 0.f);
        }
        s0 += __shfl_xor_sync(0xffffffffu, s0, 1);
        s0 += __shfl_xor_sync(0xffffffffu, s0, 2);
        s1 += __shfl_xor_sync(0xffffffffu, s1, 1);
        s1 += __shfl_xor_sync(0xffffffffu, s1, 2);
        if (t == 0) { redA[g][w] = s0; redA[g + 8][w] = s1; }
        __syncthreads();
        float S0 = 0.f, S1 = 0.f;
        #pragma unroll
        for (int wi = 0; wi < 8; wi++) { S0 += redA[g][wi]; S1 += redA[g + 8][wi]; }
        if (S0 >= 1.f) lo0 = mid0; else hi0 = mid0;
        if (S1 >= 1.f) lo1 = mid1; else hi1 = mid1;
        __syncthreads();
    }

    float tau0 = lo0, tau1 = lo1;
    for (int it = 0; it < 8; it++) {
        float s0 = 0.f, c0 = 0.f, s1 = 0.f, c1 = 0.f;
        #pragma unroll
        for (int f = 0; f < 32; f++) {
            if (acc[f][0] > tau0) { s0 += acc[f][0]; c0 += 1.f; }
            if (acc[f][1] > tau0) { s0 += acc[f][1]; c0 += 1.f; }
            if (acc[f][2] > tau1) { s1 += acc[f][2]; c1 += 1.f; }
            if (acc[f][3] > tau1) { s1 += acc[f][3]; c1 += 1.f; }
        }
        s0 += __shfl_xor_sync(0xffffffffu, s0, 1);
        s0 += __shfl_xor_sync(0xffffffffu, s0, 2);
        c0 += __shfl_xor_sync(0xffffffffu, c0, 1);
        c0 += __shfl_xor_sync(0xffffffffu, c0, 2);
        s1 += __shfl_xor_sync(0xffffffffu, s1, 1);
        s1 += __shfl_xor_sync(0xffffffffu, s1, 2);
        c1 += __shfl_xor_sync(0xffffffffu, c1, 1);
        c1 += __shfl_xor_sync(0xffffffffu, c1, 2);
        if (t == 0) { redA[g][w] = s0; redB[g][w] = c0; redA[g + 8][w] = s1; redB[g + 8][w] = c1; }
        __syncthreads();
        float S0 = 0.f, C0 = 0.f, S1 = 0.f, C1 = 0.f;
        #pragma unroll
        for (int wi = 0; wi < 8; wi++) {
            S0 += redA[g][wi]; C0 += redB[g][wi];
            S1 += redA[g + 8][wi]; C1 += redB[g + 8][wi];
        }
        tau0 = (S0 - 1.f) / C0;
        tau1 = (S1 - 1.f) / C1;
        __syncthreads();
    }

    // P = max(z - tau, 0) in place, and write attention output (the only big store)
    float* A0 = attn + (long long)bh * SS * SS;
    #pragma unroll
    for (int f = 0; f < 32; f++) {
        acc[f][0] = fmaxf(acc[f][0] - tau0, 0.f);
        acc[f][1] = fmaxf(acc[f][1] - tau0, 0.f);
        acc[f][2] = fmaxf(acc[f][2] - tau1, 0.f);
        acc[f][3] = fmaxf(acc[f][3] - tau1, 0.f);
        int kt = f >> 1, nf = f & 1;
        int col = 16 * (8 * kt + w) + nf * 8 + 2 * t;
        float2 p0 = {acc[f][0], acc[f][1]};
        float2 p1 = {acc[f][2], acc[f][3]};
        *(float2*)&A0[(long long)(row0 + g) * SS + col] = p0;
        *(float2*)&A0[(long long)(row0 + g + 8) * SS + col] = p1;
    }

    // ================= Phase C: O = P @ V =================
    float O[8][4];
    #pragma unroll
    for (int nf = 0; nf < 8; nf++)
        #pragma unroll
        for (int e = 0; e < 4; e++) O[nf][e] = 0.f;

    for (int kt = 0; kt < 16; kt++) {
        __syncthreads();
        #pragma unroll
        for (int i = 0; i < 8; i++) {
            int idx = tid + i * 256, r = idx >> 5, c = (idx & 31) * 4;
            float4 v = *(const float4*)&V[((long long)bh * DK + r) * SS + kt * 128 + c];
            cvt_hilo(v, (uint2*)&VHs[r * 136 + c], (uint2*)&VLs[r * 136 + c]);
        }
        __syncthreads();

        // transmute acc pair -> A fragment (hi/lo)
        uint32_t ah[4], al[4];
        {
            int f0 = kt * 2, f1 = f0 + 1;
            ah[0] = pack_hilo(acc[f0][0], acc[f0][1], &al[0]);
            ah[1] = pack_hilo(acc[f0][2], acc[f0][3], &al[1]);
            ah[2] = pack_hilo(acc[f1][0], acc[f1][1], &al[2]);
            ah[3] = pack_hilo(acc[f1][2], acc[f1][3], &al[3]);
        }

        #pragma unroll
        for (int p = 0; p < 4; p++) {
            int vrow = 16 * p + (lane & 7) + (lane >> 4) * 8;
            uint32_t off = (uint32_t)(vrow * 136 + 16 * w + ((lane >> 3) & 1) * 8) * 2;
            uint32_t vh4[4], vl4[4];
            ldsm4(vh4, smem_u32(VHs) + off);
            ldsm4(vl4, smem_u32(VLs) + off);
            #pragma unroll
            for (int sub = 0; sub < 2; sub++) {
                float* o = O[2 * p + sub];
                mma16(o, al, &vh4[sub * 2]);
                mma16(o, ah, &vl4[sub * 2]);
                mma16(o, ah, &vh4[sub * 2]);
            }
        }
    }

    // reduce per-warp partial O across 8 warps
    __syncthreads();
    #pragma unroll
    for (int nf = 0; nf < 8; nf++) {
        int col = nf * 8 + 2 * t;
        float2 p0 = {O[nf][0], O[nf][1]};
        float2 p1 = {O[nf][2], O[nf][3]};
        *(float2*)&Osm[w * 1024 + g * 64 + col] = p0;
        *(float2*)&Osm[w * 1024 + (g + 8) * 64 + col] = p1;
    }
    __syncthreads();

    const int b = bh >> 4, h = bh & 15;
    #pragma unroll
    for (int i = 0; i < 4; i++) {
        int idx = tid + i * 256, r = idx >> 6, d = idx & 63;
        float s = 0.f;
        #pragma unroll
        for (int wi = 0; wi < 8; wi++) s += Osm[wi * 1024 + idx];
        ao[((long long)(b * SS + row0 + r)) * DM + h * DK + d] = s;
    }
}

// ---------------------------------------------------------------------------
extern "C" void kernel_launch(void* const* d_in, const int* in_sizes, int n_in,
                              void* d_out, int out_size)
{
    const float* query = (const float*)d_in[0];
    const float* key   = (const float*)d_in[1];
    const float* value = (const float*)d_in[2];
    const float* Wq  = (const float*)d_in[3];  const float* bq  = (const float*)d_in[4];
    const float* Wk  = (const float*)d_in[5];  const float* bk  = (const float*)d_in[6];
    const float* Wv  = (const float*)d_in[7];  const float* bv  = (const float*)d_in[8];
    const float* Wfc = (const float*)d_in[9];  const float* bfc = (const float*)d_in[10];

    float* out  = (float*)d_out;
    float* attn = out + OUT_ELEMS;

    __nv_bfloat16 *pqh, *pql, *pkh, *pkl;
    float *pv, *pao;
    cudaGetSymbolAddress((void**)&pqh, g_qh);
    cudaGetSymbolAddress((void**)&pql, g_ql);
    cudaGetSymbolAddress((void**)&pkh, g_kh);
    cudaGetSymbolAddress((void**)&pkl, g_kl);
    cudaGetSymbolAddress((void**)&pv,  g_v);
    cudaGetSymbolAddress((void**)&pao, g_ao);

    const int FA_SMEM = 4608 + 2 * 128 * 72 * 2;  // 41472 B
    cudaFuncSetAttribute(fused_attn, cudaFuncAttributeMaxDynamicSharedMemorySize, FA_SMEM);

    dim3 blk(256);

    // 1) Projections: q,k -> bf16 hi/lo [bh][s][d]; v -> fp32 [bh][d][s]
    gemm_f32<1><<<dim3(DM/64, MM/128, 1), blk>>>(query, Wq, bq, nullptr, pqh, pql, DM, DM, 1.f);
    gemm_f32<1><<<dim3(DM/64, MM/128, 1), blk>>>(key,   Wk, bk, nullptr, pkh, pkl, DM, DM, 1.f);
    gemm_f32<2><<<dim3(DM/64, MM/128, 1), blk>>>(value, Wv, bv, pv, nullptr, nullptr, DM, DM, 1.f);

    // 2) fused logits + sparsemax + P write + PV
    fused_attn<<<dim3(SS/16, BB*HH, 1), blk, FA_SMEM>>>(pqh, pql, pkh, pkl, pv, attn, pao);

    // 3) output = attn_out @ Wfc^T + bfc
    gemm_f32<0><<<dim3(DM/64, MM/128, 1), blk>>>(pao, Wfc, bfc, out, nullptr, nullptr, DM, DM, 1.f);
}

// round 12
// speedup vs baseline: 1.4356x; 1.4356x over previous
#include <cuda_runtime.h>
#include <cuda_bf16.h>
#include <cstdint>

#define BB   2
#define SS   2048
#define HH   16
#define DK   64
#define DM   1024
#define MM   (BB*SS)
#define OUT_ELEMS  (4194304)

// Scratch (allocation-free rule: device globals)
__device__ __nv_bfloat16 g_qh[BB*HH*SS*DK];   // q hi, [bh][s][d]
__device__ __nv_bfloat16 g_ql[BB*HH*SS*DK];   // q lo
__device__ __nv_bfloat16 g_kh[BB*HH*SS*DK];   // k hi
__device__ __nv_bfloat16 g_kl[BB*HH*SS*DK];   // k lo
__device__ float g_v [BB*HH*DK*SS];           // v TRANSPOSED fp32: [bh][d][s]
__device__ float g_ao[MM*DM];                 // attn_out, (b,s,h,d) flat

// single dynamic-smem symbol shared by all kernels (one TU-wide extern)
extern __shared__ char dynsm[];

// ---------------------------------------------------------------------------
__device__ __forceinline__ void mma16(float* c, const uint32_t* a, const uint32_t* b) {
    asm volatile("mma.sync.aligned.m16n8k16.row.col.f32.bf16.bf16.f32 "
        "{%0,%1,%2,%3},{%4,%5,%6,%7},{%8,%9},{%0,%1,%2,%3};"
        : "+f"(c[0]), "+f"(c[1]), "+f"(c[2]), "+f"(c[3])
        : "r"(a[0]), "r"(a[1]), "r"(a[2]), "r"(a[3]), "r"(b[0]), "r"(b[1]));
}

__device__ __forceinline__ void ldsm4(uint32_t* r, uint32_t addr) {
    asm volatile("ldmatrix.sync.aligned.m8n8.x4.shared.b16 {%0,%1,%2,%3}, [%4];"
        : "=r"(r[0]), "=r"(r[1]), "=r"(r[2]), "=r"(r[3]) : "r"(addr));
}

__device__ __forceinline__ uint32_t smem_u32(const void* p) {
    return (uint32_t)__cvta_generic_to_shared(p);
}

__device__ __forceinline__ void cp16(uint32_t dst, const void* src) {
    asm volatile("cp.async.cg.shared.global [%0], [%1], 16;" :: "r"(dst), "l"(src));
}

// convert 4 floats -> 4 hi bf16 (8B) + 4 lo bf16 (8B)
__device__ __forceinline__ void cvt_hilo(const float4 v, uint2* ph, uint2* pl) {
    __nv_bfloat162 h0 = __floats2bfloat162_rn(v.x, v.y);
    __nv_bfloat162 h1 = __floats2bfloat162_rn(v.z, v.w);
    __nv_bfloat162 l0 = __floats2bfloat162_rn(v.x - __bfloat162float(h0.x),
                                              v.y - __bfloat162float(h0.y));
    __nv_bfloat162 l1 = __floats2bfloat162_rn(v.z - __bfloat162float(h1.x),
                                              v.w - __bfloat162float(h1.y));
    *ph = make_uint2(*(uint32_t*)&h0, *(uint32_t*)&h1);
    *pl = make_uint2(*(uint32_t*)&l0, *(uint32_t*)&l1);
}

// ===========================================================================
// fp32-input bf16x3 NT GEMM (proven R7). C = scale*(A @ B^T)(+bias).
// MODE: 0 row-major fp32 C; 1 bf16 hi/lo scatter [b,h,s,d]; 2 fp32 scatter [b,h,d,s]
// ===========================================================================
template<int MODE>
__global__ void __launch_bounds__(256, 2) gemm_f32(
    const float* __restrict__ A, const float* __restrict__ B,
    const float* __restrict__ bias, float* __restrict__ C,
    __nv_bfloat16* __restrict__ Ch, __nv_bfloat16* __restrict__ Cl,
    int N, int K, float scale)
{
    constexpr int BK = 32, SK = 40;

    __shared__ __nv_bfloat16 Ah[128 * SK], Al[128 * SK];
    __shared__ __nv_bfloat16 Bh[64 * SK],  Bl[64 * SK];

    const int tid = threadIdx.x, w = tid >> 5, lane = tid & 31;
    const int g = lane >> 2, t = lane & 3;
    const int m0 = blockIdx.y * 128, n0 = blockIdx.x * 64;
    const int wm0 = (w & 3) * 32, wn0 = (w >> 2) * 32;

    const uint32_t ah_b = smem_u32(Ah), al_b = smem_u32(Al);
    const uint32_t bh_b = smem_u32(Bh), bl_b = smem_u32(Bl);

    float acc[2][4][4];
    #pragma unroll
    for (int i = 0; i < 2; i++)
        #pragma unroll
        for (int j = 0; j < 4; j++)
            #pragma unroll
            for (int e = 0; e < 4; e++) acc[i][j][e] = 0.f;

    float4 ra[4], rb[2];
    #pragma unroll
    for (int i = 0; i < 4; i++) {
        int idx = tid + i * 256;
        ra[i] = *(const float4*)(A + (long long)(m0 + (idx >> 3)) * K + (idx & 7) * 4);
    }
    #pragma unroll
    for (int i = 0; i < 2; i++) {
        int idx = tid + i * 256;
        rb[i] = *(const float4*)(B + (long long)(n0 + (idx >> 3)) * K + (idx & 7) * 4);
    }

    for (int k0 = 0; k0 < K; k0 += BK) {
        __syncthreads();
        #pragma unroll
        for (int i = 0; i < 4; i++) {
            int idx = tid + i * 256, r = idx >> 3, c = (idx & 7) * 4;
            cvt_hilo(ra[i], (uint2*)&Ah[r * SK + c], (uint2*)&Al[r * SK + c]);
        }
        #pragma unroll
        for (int i = 0; i < 2; i++) {
            int idx = tid + i * 256, r = idx >> 3, c = (idx & 7) * 4;
            cvt_hilo(rb[i], (uint2*)&Bh[r * SK + c], (uint2*)&Bl[r * SK + c]);
        }
        __syncthreads();

        if (k0 + BK < K) {
            #pragma unroll
            for (int i = 0; i < 4; i++) {
                int idx = tid + i * 256;
                ra[i] = *(const float4*)(A + (long long)(m0 + (idx >> 3)) * K + k0 + BK + (idx & 7) * 4);
            }
            #pragma unroll
            for (int i = 0; i < 2; i++) {
                int idx = tid + i * 256;
                rb[i] = *(const float4*)(B + (long long)(n0 + (idx >> 3)) * K + k0 + BK + (idx & 7) * 4);
            }
        }

        #pragma unroll
        for (int ks = 0; ks < 2; ks++) {
            const int arow = wm0 + (lane & 7) + ((lane >> 3) & 1) * 8;
            const int acol = ks * 16 + (lane >> 4) * 8;
            const int brow = wn0 + (lane & 7) + (lane >> 4) * 8;
            const int bcol = ((lane >> 3) & 1) * 8 + ks * 16;

            uint32_t af[2][4], afl[2][4], bf[2][4], bfl[2][4];
            #pragma unroll
            for (int f = 0; f < 2; f++) {
                uint32_t off = ((arow + f * 16) * SK + acol) * 2;
                ldsm4(af[f],  ah_b + off);
                ldsm4(afl[f], al_b + off);
            }
            #pragma unroll
            for (int p = 0; p < 2; p++) {
                uint32_t off = ((brow + p * 16) * SK + bcol) * 2;
                ldsm4(bf[p],  bh_b + off);
                ldsm4(bfl[p], bl_b + off);
            }

            #pragma unroll
            for (int mf = 0; mf < 2; mf++)
                #pragma unroll
                for (int nf = 0; nf < 4; nf++) {
                    const uint32_t* bp = &bf[nf >> 1][(nf & 1) * 2];
                    const uint32_t* lp = &bfl[nf >> 1][(nf & 1) * 2];
                    mma16(acc[mf][nf], afl[mf], bp);
                    mma16(acc[mf][nf], af[mf],  lp);
                    mma16(acc[mf][nf], af[mf],  bp);
                }
        }
    }

    #pragma unroll
    for (int mf = 0; mf < 2; mf++) {
        #pragma unroll
        for (int nf = 0; nf < 4; nf++) {
            const int gn = n0 + wn0 + nf * 8 + 2 * t;
            float b0 = 0.f, b1 = 0.f;
            if (bias) { b0 = __ldg(&bias[gn]); b1 = __ldg(&bias[gn + 1]); }
            #pragma unroll
            for (int h = 0; h < 2; h++) {
                const int gm = m0 + wm0 + mf * 16 + g + h * 8;
                float v0 = acc[mf][nf][h * 2 + 0] * scale + b0;
                float v1 = acc[mf][nf][h * 2 + 1] * scale + b1;
                if (MODE == 0) {
                    float2 p = {v0, v1};
                    *(float2*)&C[(long long)gm * N + gn] = p;
                } else if (MODE == 1) {
                    int b = gm >> 11, s = gm & (SS - 1);
                    int hh = gn >> 6, d = gn & 63;
                    long long idx = (((long long)(b * HH + hh)) * SS + s) * DK + d;
                    __nv_bfloat162 hp = __floats2bfloat162_rn(v0, v1);
                    __nv_bfloat162 lp = __floats2bfloat162_rn(v0 - __bfloat162float(hp.x),
                                                              v1 - __bfloat162float(hp.y));
                    *(uint32_t*)&Ch[idx] = *(uint32_t*)&hp;
                    *(uint32_t*)&Cl[idx] = *(uint32_t*)&lp;
                } else { // MODE 2
                    int b = gm >> 11, s = gm & (SS - 1);
                    int hh = gn >> 6, d = gn & 63;
                    C[(((long long)(b * HH + hh)) * DK + d) * SS + s] = v0;
                    C[(((long long)(b * HH + hh)) * DK + d + 1) * SS + s] = v1;
                }
            }
        }
    }
}

// ===========================================================================
// Logits GEMM (proven R7): bf16 hi/lo inputs via cp.async. C=(q@k^T)/8 per head.
// ===========================================================================
__global__ void __launch_bounds__(256, 2) gemm_lg(
    const __nv_bfloat16* __restrict__ Qh, const __nv_bfloat16* __restrict__ Ql,
    const __nv_bfloat16* __restrict__ Kh, const __nv_bfloat16* __restrict__ Kl,
    float* __restrict__ C)
{
    constexpr int SK = 72;
    __nv_bfloat16* sm = (__nv_bfloat16*)dynsm;
    __nv_bfloat16* tiles[4] = { sm, sm + 128 * SK, sm + 2 * 128 * SK, sm + 3 * 128 * SK };

    const int bh = blockIdx.z;
    const int tid = threadIdx.x, w = tid >> 5, lane = tid & 31;
    const int g = lane >> 2, t = lane & 3;
    const int m0 = blockIdx.y * 128, n0 = blockIdx.x * 128;
    const int wm0 = (w & 3) * 32, wn0 = (w >> 2) * 64;

    const __nv_bfloat16* srcs[4] = {
        Qh + (long long)bh * SS * DK + (long long)m0 * DK,
        Ql + (long long)bh * SS * DK + (long long)m0 * DK,
        Kh + (long long)bh * SS * DK + (long long)n0 * DK,
        Kl + (long long)bh * SS * DK + (long long)n0 * DK };

    #pragma unroll
    for (int a = 0; a < 4; a++) {
        uint32_t dst = smem_u32(tiles[a]);
        #pragma unroll
        for (int i = 0; i < 4; i++) {
            int idx = tid + i * 256;
            int r = idx >> 3, c = idx & 7;
            cp16(dst + (r * SK + c * 8) * 2, srcs[a] + r * 64 + c * 8);
        }
    }
    asm volatile("cp.async.commit_group;");
    asm volatile("cp.async.wait_group 0;");
    __syncthreads();

    const uint32_t ah_b = smem_u32(tiles[0]), al_b = smem_u32(tiles[1]);
    const uint32_t bh_b = smem_u32(tiles[2]), bl_b = smem_u32(tiles[3]);

    float acc[2][8][4];
    #pragma unroll
    for (int i = 0; i < 2; i++)
        #pragma unroll
        for (int j = 0; j < 8; j++)
            #pragma unroll
            for (int e = 0; e < 4; e++) acc[i][j][e] = 0.f;

    #pragma unroll
    for (int ks = 0; ks < 4; ks++) {
        const int arow = wm0 + (lane & 7) + ((lane >> 3) & 1) * 8;
        const int acol = ks * 16 + (lane >> 4) * 8;
        const int brow = wn0 + (lane & 7) + (lane >> 4) * 8;
        const int bcol = ((lane >> 3) & 1) * 8 + ks * 16;

        uint32_t af[2][4], afl[2][4], bf[4][4], bfl[4][4];
        #pragma unroll
        for (int f = 0; f < 2; f++) {
            uint32_t off = ((arow + f * 16) * SK + acol) * 2;
            ldsm4(af[f],  ah_b + off);
            ldsm4(afl[f], al_b + off);
        }
        #pragma unroll
        for (int p = 0; p < 4; p++) {
            uint32_t off = ((brow + p * 16) * SK + bcol) * 2;
            ldsm4(bf[p],  bh_b + off);
            ldsm4(bfl[p], bl_b + off);
        }

        #pragma unroll
        for (int mf = 0; mf < 2; mf++)
            #pragma unroll
            for (int nf = 0; nf < 8; nf++) {
                const uint32_t* bp = &bf[nf >> 1][(nf & 1) * 2];
                const uint32_t* lp = &bfl[nf >> 1][(nf & 1) * 2];
                mma16(acc[mf][nf], afl[mf], bp);
                mma16(acc[mf][nf], af[mf],  lp);
                mma16(acc[mf][nf], af[mf],  bp);
            }
    }

    float* Cb = C + (long long)bh * SS * SS;
    #pragma unroll
    for (int mf = 0; mf < 2; mf++)
        #pragma unroll
        for (int nf = 0; nf < 8; nf++) {
            const int gn = n0 + wn0 + nf * 8 + 2 * t;
            #pragma unroll
            for (int h = 0; h < 2; h++) {
                const int gm = m0 + wm0 + mf * 16 + g + h * 8;
                float2 p = {acc[mf][nf][h * 2] * 0.125f, acc[mf][nf][h * 2 + 1] * 0.125f};
                *(float2*)&Cb[(long long)gm * SS + gn] = p;
            }
        }
}

// ===========================================================================
// Fused sparsemax + PV. Grid (SS/128, BB*HH), 256 thr.
// Pass 1: warp-per-row tau over the CTA's 128-row strip (R7 sparsemax math).
// Pass 2: per 128-wide k-tile: re-read logits (L2-hot), apply relu(z-tau),
//         write final P to attn (d_out), stage bf16 hi/lo, mma into O.
// ===========================================================================
__global__ void __launch_bounds__(256) fused_spv(
    float* __restrict__ attn, const float* __restrict__ V, float* __restrict__ ao)
{
    constexpr int SKP = 136;  // halves per row (272B: 17r mod 8 -> conflict-free ldsm)
    char* sm = dynsm;
    float* tau_s = (float*)sm;                              // 128 floats
    __nv_bfloat16* PH = (__nv_bfloat16*)(sm + 512);         // 128 x 136
    __nv_bfloat16* PL = (__nv_bfloat16*)(sm + 512 + 34816);
    __nv_bfloat16* VH = (__nv_bfloat16*)(sm + 512 + 69632); // 64 x 136
    __nv_bfloat16* VL = (__nv_bfloat16*)(sm + 512 + 87040);

    const int tid = threadIdx.x, w = tid >> 5, lane = tid & 31;
    const int g = lane >> 2, t = lane & 3;
    const int q0 = blockIdx.x * 128;
    const int bh = blockIdx.y;
    float* A0 = attn + (long long)bh * SS * SS;

    // ---------------- Pass 1: tau per row (warp-per-row, 16 iters) ---------
    for (int it = 0; it < 16; it++) {
        const int rl = it * 8 + w;
        const float* z = A0 + (long long)(q0 + rl) * SS;

        float4 v[16];
        #pragma unroll
        for (int i = 0; i < 16; i++) v[i] = *(const float4*)(z + i * 128 + lane * 4);

        float mx = -1e30f;
        #pragma unroll
        for (int i = 0; i < 16; i++)
            mx = fmaxf(mx, fmaxf(fmaxf(v[i].x, v[i].y), fmaxf(v[i].z, v[i].w)));
        #pragma unroll
        for (int o = 16; o; o >>= 1) mx = fmaxf(mx, __shfl_xor_sync(0xffffffffu, mx, o));

        float lo = mx - 1.f, hi = mx;
        for (int itb = 0; itb < 12; itb++) {
            float mid = 0.5f * (lo + hi);
            float s = 0.f;
            #pragma unroll
            for (int i = 0; i < 16; i++) {
                s += fmaxf(v[i].x - mid, 0.f) + fmaxf(v[i].y - mid, 0.f);
                s += fmaxf(v[i].z - mid, 0.f) + fmaxf(v[i].w - mid, 0.f);
            }
            #pragma unroll
            for (int o = 16; o; o >>= 1) s += __shfl_xor_sync(0xffffffffu, s, o);
            if (s >= 1.f) lo = mid; else hi = mid;
        }

        float tau = lo;
        for (int itm = 0; itm < 8; itm++) {
            float s = 0.f, c = 0.f;
            #pragma unroll
            for (int i = 0; i < 16; i++) {
                if (v[i].x > tau) { s += v[i].x; c += 1.f; }
                if (v[i].y > tau) { s += v[i].y; c += 1.f; }
                if (v[i].z > tau) { s += v[i].z; c += 1.f; }
                if (v[i].w > tau) { s += v[i].w; c += 1.f; }
            }
            #pragma unroll
            for (int o = 16; o; o >>= 1) {
                s += __shfl_xor_sync(0xffffffffu, s, o);
                c += __shfl_xor_sync(0xffffffffu, c, o);
            }
            float nt = (s - 1.f) / c;   // c >= 1 (row max in support)
            if (nt == tau) break;
            tau = nt;
        }
        if (lane == 0) tau_s[rl] = tau;
    }
    __syncthreads();

    // ---------------- Pass 2: relu + P write + PV mma ----------------------
    const int wq0 = (w & 3) * 32, wd0 = (w >> 2) * 32;
    float O[2][4][4];
    #pragma unroll
    for (int i = 0; i < 2; i++)
        #pragma unroll
        for (int j = 0; j < 4; j++)
            #pragma unroll
            for (int e = 0; e < 4; e++) O[i][j][e] = 0.f;

    for (int kt = 0; kt < 16; kt++) {
        if (kt) __syncthreads();
        // stage V tile 64d x 128k (fp32 [bh][d][s])
        #pragma unroll
        for (int i = 0; i < 8; i++) {
            int idx = tid + i * 256, r = idx >> 5, c = (idx & 31) * 4;
            float4 v = *(const float4*)&V[((long long)bh * DK + r) * SS + kt * 128 + c];
            cvt_hilo(v, (uint2*)&VH[r * SKP + c], (uint2*)&VL[r * SKP + c]);
        }
        // stage P tile 128q x 128k: read logits, relu, write P, convert
        #pragma unroll
        for (int i = 0; i < 16; i++) {
            int idx = tid + i * 256, r = idx >> 5, c = (idx & 31) * 4;
            float* gp = A0 + (long long)(q0 + r) * SS + kt * 128 + c;
            float4 z = *(const float4*)gp;
            float tau = tau_s[r];
            z.x = fmaxf(z.x - tau, 0.f);
            z.y = fmaxf(z.y - tau, 0.f);
            z.z = fmaxf(z.z - tau, 0.f);
            z.w = fmaxf(z.w - tau, 0.f);
            *(float4*)gp = z;
            cvt_hilo(z, (uint2*)&PH[r * SKP + c], (uint2*)&PL[r * SKP + c]);
        }
        __syncthreads();

        #pragma unroll
        for (int ks = 0; ks < 8; ks++) {
            const int arow = wq0 + (lane & 7) + ((lane >> 3) & 1) * 8;
            const int acol = ks * 16 + (lane >> 4) * 8;
            const int brow = wd0 + (lane & 7) + (lane >> 4) * 8;
            const int bcol = ((lane >> 3) & 1) * 8 + ks * 16;

            uint32_t af[2][4], afl[2][4], bf[2][4], bfl[2][4];
            #pragma unroll
            for (int f = 0; f < 2; f++) {
                uint32_t off = ((arow + f * 16) * SKP + acol) * 2;
                ldsm4(af[f],  smem_u32(PH) + off);
                ldsm4(afl[f], smem_u32(PL) + off);
            }
            #pragma unroll
            for (int p = 0; p < 2; p++) {
                uint32_t off = ((brow + p * 16) * SKP + bcol) * 2;
                ldsm4(bf[p],  smem_u32(VH) + off);
                ldsm4(bfl[p], smem_u32(VL) + off);
            }

            #pragma unroll
            for (int mf = 0; mf < 2; mf++)
                #pragma unroll
                for (int nf = 0; nf < 4; nf++) {
                    const uint32_t* bp = &bf[nf >> 1][(nf & 1) * 2];
                    const uint32_t* lp = &bfl[nf >> 1][(nf & 1) * 2];
                    mma16(O[mf][nf], afl[mf], bp);
                    mma16(O[mf][nf], af[mf],  lp);
                    mma16(O[mf][nf], af[mf],  bp);
                }
        }
    }

    // epilogue -> ao (b,s,h,d) flat
    const int b = bh >> 4, head = bh & 15;
    #pragma unroll
    for (int mf = 0; mf < 2; mf++)
        #pragma unroll
        for (int nf = 0; nf < 4; nf++) {
            const int gn = wd0 + nf * 8 + 2 * t;
            #pragma unroll
            for (int h2 = 0; h2 < 2; h2++) {
                const int gm = q0 + wq0 + mf * 16 + g + h2 * 8;
                float2 p = {O[mf][nf][h2 * 2], O[mf][nf][h2 * 2 + 1]};
                *(float2*)&ao[((long long)(b * SS + gm)) * DM + head * DK + gn] = p;
            }
        }
}

// ---------------------------------------------------------------------------
extern "C" void kernel_launch(void* const* d_in, const int* in_sizes, int n_in,
                              void* d_out, int out_size)
{
    const float* query = (const float*)d_in[0];
    const float* key   = (const float*)d_in[1];
    const float* value = (const float*)d_in[2];
    const float* Wq  = (const float*)d_in[3];  const float* bq  = (const float*)d_in[4];
    const float* Wk  = (const float*)d_in[5];  const float* bk  = (const float*)d_in[6];
    const float* Wv  = (const float*)d_in[7];  const float* bv  = (const float*)d_in[8];
    const float* Wfc = (const float*)d_in[9];  const float* bfc = (const float*)d_in[10];

    float* out  = (float*)d_out;
    float* attn = out + OUT_ELEMS;

    __nv_bfloat16 *pqh, *pql, *pkh, *pkl;
    float *pv, *pao;
    cudaGetSymbolAddress((void**)&pqh, g_qh);
    cudaGetSymbolAddress((void**)&pql, g_ql);
    cudaGetSymbolAddress((void**)&pkh, g_kh);
    cudaGetSymbolAddress((void**)&pkl, g_kl);
    cudaGetSymbolAddress((void**)&pv,  g_v);
    cudaGetSymbolAddress((void**)&pao, g_ao);

    const int LG_SMEM = 4 * 128 * 72 * 2;                 // 73728 B
    const int SPV_SMEM = 512 + 2 * 34816 + 2 * 17408;     // 104960 B
    cudaFuncSetAttribute(gemm_lg, cudaFuncAttributeMaxDynamicSharedMemorySize, LG_SMEM);
    cudaFuncSetAttribute(fused_spv, cudaFuncAttributeMaxDynamicSharedMemorySize, SPV_SMEM);

    dim3 blk(256);

    // 1) Projections: q,k -> bf16 hi/lo [bh][s][d]; v -> fp32 [bh][d][s]
    gemm_f32<1><<<dim3(DM/64, MM/128, 1), blk>>>(query, Wq, bq, nullptr, pqh, pql, DM, DM, 1.f);
    gemm_f32<1><<<dim3(DM/64, MM/128, 1), blk>>>(key,   Wk, bk, nullptr, pkh, pkl, DM, DM, 1.f);
    gemm_f32<2><<<dim3(DM/64, MM/128, 1), blk>>>(value, Wv, bv, pv, nullptr, nullptr, DM, DM, 1.f);

    // 2) logits = q @ k^T / 8 -> attention slice of d_out
    gemm_lg<<<dim3(SS/128, SS/128, BB*HH), blk, LG_SMEM>>>(pqh, pql, pkh, pkl, attn);

    // 3) fused sparsemax (tau + relu + P write) + PV -> attn final, ao
    fused_spv<<<dim3(SS/128, BB*HH, 1), blk, SPV_SMEM>>>(attn, pv, pao);

    // 4) output = attn_out @ Wfc^T + bfc
    gemm_f32<0><<<dim3(DM/64, MM/128, 1), blk>>>(pao, Wfc, bfc, out, nullptr, nullptr, DM, DM, 1.f);
}

// round 13
// speedup vs baseline: 1.8109x; 1.2615x over previous
#include <cuda_runtime.h>
#include <cuda_bf16.h>
#include <cstdint>

#define BB   2
#define SS   2048
#define HH   16
#define DK   64
#define DM   1024
#define MM   (BB*SS)
#define OUT_ELEMS  (4194304)

// Scratch (allocation-free rule: device globals)
__device__ __nv_bfloat16 g_qh[BB*HH*SS*DK];   // q hi, [bh][s][d]
__device__ __nv_bfloat16 g_ql[BB*HH*SS*DK];   // q lo
__device__ __nv_bfloat16 g_kh[BB*HH*SS*DK];   // k hi
__device__ __nv_bfloat16 g_kl[BB*HH*SS*DK];   // k lo
__device__ float g_v [BB*HH*DK*SS];           // v TRANSPOSED fp32: [bh][d][s]
__device__ float g_ao[MM*DM];                 // attn_out, (b,s,h,d) flat

// single dynamic-smem symbol (used by gemm_lg)
extern __shared__ char dynsm[];

// ---------------------------------------------------------------------------
__device__ __forceinline__ void mma16(float* c, const uint32_t* a, const uint32_t* b) {
    asm volatile("mma.sync.aligned.m16n8k16.row.col.f32.bf16.bf16.f32 "
        "{%0,%1,%2,%3},{%4,%5,%6,%7},{%8,%9},{%0,%1,%2,%3};"
        : "+f"(c[0]), "+f"(c[1]), "+f"(c[2]), "+f"(c[3])
        : "r"(a[0]), "r"(a[1]), "r"(a[2]), "r"(a[3]), "r"(b[0]), "r"(b[1]));
}

__device__ __forceinline__ void ldsm4(uint32_t* r, uint32_t addr) {
    asm volatile("ldmatrix.sync.aligned.m8n8.x4.shared.b16 {%0,%1,%2,%3}, [%4];"
        : "=r"(r[0]), "=r"(r[1]), "=r"(r[2]), "=r"(r[3]) : "r"(addr));
}

__device__ __forceinline__ uint32_t smem_u32(const void* p) {
    return (uint32_t)__cvta_generic_to_shared(p);
}

__device__ __forceinline__ void cp16(uint32_t dst, const void* src) {
    asm volatile("cp.async.cg.shared.global [%0], [%1], 16;" :: "r"(dst), "l"(src));
}

// convert 4 floats -> 4 hi bf16 (8B) + 4 lo bf16 (8B)
__device__ __forceinline__ void cvt_hilo(const float4 v, uint2* ph, uint2* pl) {
    __nv_bfloat162 h0 = __floats2bfloat162_rn(v.x, v.y);
    __nv_bfloat162 h1 = __floats2bfloat162_rn(v.z, v.w);
    __nv_bfloat162 l0 = __floats2bfloat162_rn(v.x - __bfloat162float(h0.x),
                                              v.y - __bfloat162float(h0.y));
    __nv_bfloat162 l1 = __floats2bfloat162_rn(v.z - __bfloat162float(h1.x),
                                              v.w - __bfloat162float(h1.y));
    *ph = make_uint2(*(uint32_t*)&h0, *(uint32_t*)&h1);
    *pl = make_uint2(*(uint32_t*)&l0, *(uint32_t*)&l1);
}

// ===========================================================================
// gemm_w: fp32-input bf16x3 NT GEMM, 128x128 tile, BK=16. 8 warps (4Mx2N),
// warp tile 32x64. C = scale*(A@B^T)(+bias).
// MODE: 0 row-major fp32 C; 1 bf16 hi/lo scatter [b,h,s,d]; 2 fp32 scatter [b,h,d,s]
// ===========================================================================
template<int MODE>
__global__ void __launch_bounds__(256, 2) gemm_w(
    const float* __restrict__ A, const float* __restrict__ B,
    const float* __restrict__ bias, float* __restrict__ C,
    __nv_bfloat16* __restrict__ Ch, __nv_bfloat16* __restrict__ Cl,
    int N, int K, float scale)
{
    constexpr int BK = 16, SK = 24;  // 48B rows: 3r mod 8 -> conflict-free ldsm

    __shared__ __nv_bfloat16 Ah[128 * SK], Al[128 * SK];
    __shared__ __nv_bfloat16 Bh[128 * SK], Bl[128 * SK];

    const int tid = threadIdx.x, w = tid >> 5, lane = tid & 31;
    const int g = lane >> 2, t = lane & 3;
    const int m0 = blockIdx.y * 128, n0 = blockIdx.x * 128;
    const int wm0 = (w & 3) * 32, wn0 = (w >> 2) * 64;

    const uint32_t ah_b = smem_u32(Ah), al_b = smem_u32(Al);
    const uint32_t bh_b = smem_u32(Bh), bl_b = smem_u32(Bl);

    float acc[2][8][4];
    #pragma unroll
    for (int i = 0; i < 2; i++)
        #pragma unroll
        for (int j = 0; j < 8; j++)
            #pragma unroll
            for (int e = 0; e < 4; e++) acc[i][j][e] = 0.f;

    // global loads: 2 float4/thread each for A and B (r=idx>>2, c=(idx&3)*4)
    float4 ra[2], rb[2];
    #pragma unroll
    for (int i = 0; i < 2; i++) {
        int idx = tid + i * 256;
        ra[i] = *(const float4*)(A + (long long)(m0 + (idx >> 2)) * K + (idx & 3) * 4);
        rb[i] = *(const float4*)(B + (long long)(n0 + (idx >> 2)) * K + (idx & 3) * 4);
    }

    for (int k0 = 0; k0 < K; k0 += BK) {
        __syncthreads();
        #pragma unroll
        for (int i = 0; i < 2; i++) {
            int idx = tid + i * 256, r = idx >> 2, c = (idx & 3) * 4;
            cvt_hilo(ra[i], (uint2*)&Ah[r * SK + c], (uint2*)&Al[r * SK + c]);
            cvt_hilo(rb[i], (uint2*)&Bh[r * SK + c], (uint2*)&Bl[r * SK + c]);
        }
        __syncthreads();

        if (k0 + BK < K) {
            #pragma unroll
            for (int i = 0; i < 2; i++) {
                int idx = tid + i * 256;
                ra[i] = *(const float4*)(A + (long long)(m0 + (idx >> 2)) * K + k0 + BK + (idx & 3) * 4);
                rb[i] = *(const float4*)(B + (long long)(n0 + (idx >> 2)) * K + k0 + BK + (idx & 3) * 4);
            }
        }

        const int arow = wm0 + (lane & 7) + ((lane >> 3) & 1) * 8;
        const int acol = (lane >> 4) * 8;
        const int brow = wn0 + (lane & 7) + (lane >> 4) * 8;
        const int bcol = ((lane >> 3) & 1) * 8;

        uint32_t af[2][4], afl[2][4], bf[4][4], bfl[4][4];
        #pragma unroll
        for (int f = 0; f < 2; f++) {
            uint32_t off = ((arow + f * 16) * SK + acol) * 2;
            ldsm4(af[f],  ah_b + off);
            ldsm4(afl[f], al_b + off);
        }
        #pragma unroll
        for (int p = 0; p < 4; p++) {
            uint32_t off = ((brow + p * 16) * SK + bcol) * 2;
            ldsm4(bf[p],  bh_b + off);
            ldsm4(bfl[p], bl_b + off);
        }

        #pragma unroll
        for (int mf = 0; mf < 2; mf++)
            #pragma unroll
            for (int nf = 0; nf < 8; nf++) {
                const uint32_t* bp = &bf[nf >> 1][(nf & 1) * 2];
                const uint32_t* lp = &bfl[nf >> 1][(nf & 1) * 2];
                mma16(acc[mf][nf], afl[mf], bp);
                mma16(acc[mf][nf], af[mf],  lp);
                mma16(acc[mf][nf], af[mf],  bp);
            }
    }

    #pragma unroll
    for (int mf = 0; mf < 2; mf++) {
        #pragma unroll
        for (int nf = 0; nf < 8; nf++) {
            const int gn = n0 + wn0 + nf * 8 + 2 * t;
            float b0 = 0.f, b1 = 0.f;
            if (bias) { b0 = __ldg(&bias[gn]); b1 = __ldg(&bias[gn + 1]); }
            #pragma unroll
            for (int h = 0; h < 2; h++) {
                const int gm = m0 + wm0 + mf * 16 + g + h * 8;
                float v0 = acc[mf][nf][h * 2 + 0] * scale + b0;
                float v1 = acc[mf][nf][h * 2 + 1] * scale + b1;
                if (MODE == 0) {
                    float2 p = {v0, v1};
                    *(float2*)&C[(long long)gm * N + gn] = p;
                } else if (MODE == 1) {
                    int b = gm >> 11, s = gm & (SS - 1);
                    int hh = gn >> 6, d = gn & 63;
                    long long idx = (((long long)(b * HH + hh)) * SS + s) * DK + d;
                    __nv_bfloat162 hp = __floats2bfloat162_rn(v0, v1);
                    __nv_bfloat162 lp = __floats2bfloat162_rn(v0 - __bfloat162float(hp.x),
                                                              v1 - __bfloat162float(hp.y));
                    *(uint32_t*)&Ch[idx] = *(uint32_t*)&hp;
                    *(uint32_t*)&Cl[idx] = *(uint32_t*)&lp;
                } else { // MODE 2
                    int b = gm >> 11, s = gm & (SS - 1);
                    int hh = gn >> 6, d = gn & 63;
                    C[(((long long)(b * HH + hh)) * DK + d) * SS + s] = v0;
                    C[(((long long)(b * HH + hh)) * DK + d + 1) * SS + s] = v1;
                }
            }
        }
    }
}

// ===========================================================================
// gemm_pv (proven R7 PV): P @ V^T per head, 128x64 tile, BK=32.
// A = attn[bh] (fp32 P), B = V[bh] ([d][s] fp32). Out: (b,s,h,d) flat.
// ===========================================================================
__global__ void __launch_bounds__(256, 2) gemm_pv(
    const float* __restrict__ attn, const float* __restrict__ V,
    float* __restrict__ ao)
{
    constexpr int BK = 32, SK = 40;

    __shared__ __nv_bfloat16 Ah[128 * SK], Al[128 * SK];
    __shared__ __nv_bfloat16 Bh[64 * SK],  Bl[64 * SK];

    const int bz = blockIdx.z;
    const float* A = attn + (long long)bz * SS * SS;
    const float* B = V + (long long)bz * DK * SS;
    const int K = SS;

    const int tid = threadIdx.x, w = tid >> 5, lane = tid & 31;
    const int g = lane >> 2, t = lane & 3;
    const int m0 = blockIdx.y * 128;
    const int wm0 = (w & 3) * 32, wn0 = (w >> 2) * 32;

    const uint32_t ah_b = smem_u32(Ah), al_b = smem_u32(Al);
    const uint32_t bh_b = smem_u32(Bh), bl_b = smem_u32(Bl);

    float acc[2][4][4];
    #pragma unroll
    for (int i = 0; i < 2; i++)
        #pragma unroll
        for (int j = 0; j < 4; j++)
            #pragma unroll
            for (int e = 0; e < 4; e++) acc[i][j][e] = 0.f;

    float4 ra[4], rb[2];
    #pragma unroll
    for (int i = 0; i < 4; i++) {
        int idx = tid + i * 256;
        ra[i] = *(const float4*)(A + (long long)(m0 + (idx >> 3)) * K + (idx & 7) * 4);
    }
    #pragma unroll
    for (int i = 0; i < 2; i++) {
        int idx = tid + i * 256;
        rb[i] = *(const float4*)(B + (long long)(idx >> 3) * K + (idx & 7) * 4);
    }

    for (int k0 = 0; k0 < K; k0 += BK) {
        __syncthreads();
        #pragma unroll
        for (int i = 0; i < 4; i++) {
            int idx = tid + i * 256, r = idx >> 3, c = (idx & 7) * 4;
            cvt_hilo(ra[i], (uint2*)&Ah[r * SK + c], (uint2*)&Al[r * SK + c]);
        }
        #pragma unroll
        for (int i = 0; i < 2; i++) {
            int idx = tid + i * 256, r = idx >> 3, c = (idx & 7) * 4;
            cvt_hilo(rb[i], (uint2*)&Bh[r * SK + c], (uint2*)&Bl[r * SK + c]);
        }
        __syncthreads();

        if (k0 + BK < K) {
            #pragma unroll
            for (int i = 0; i < 4; i++) {
                int idx = tid + i * 256;
                ra[i] = *(const float4*)(A + (long long)(m0 + (idx >> 3)) * K + k0 + BK + (idx & 7) * 4);
            }
            #pragma unroll
            for (int i = 0; i < 2; i++) {
                int idx = tid + i * 256;
                rb[i] = *(const float4*)(B + (long long)(idx >> 3) * K + k0 + BK + (idx & 7) * 4);
            }
        }

        #pragma unroll
        for (int ks = 0; ks < 2; ks++) {
            const int arow = wm0 + (lane & 7) + ((lane >> 3) & 1) * 8;
            const int acol = ks * 16 + (lane >> 4) * 8;
            const int brow = wn0 + (lane & 7) + (lane >> 4) * 8;
            const int bcol = ((lane >> 3) & 1) * 8 + ks * 16;

            uint32_t af[2][4], afl[2][4], bf[2][4], bfl[2][4];
            #pragma unroll
            for (int f = 0; f < 2; f++) {
                uint32_t off = ((arow + f * 16) * SK + acol) * 2;
                ldsm4(af[f],  ah_b + off);
                ldsm4(afl[f], al_b + off);
            }
            #pragma unroll
            for (int p = 0; p < 2; p++) {
                uint32_t off = ((brow + p * 16) * SK + bcol) * 2;
                ldsm4(bf[p],  bh_b + off);
                ldsm4(bfl[p], bl_b + off);
            }

            #pragma unroll
            for (int mf = 0; mf < 2; mf++)
                #pragma unroll
                for (int nf = 0; nf < 4; nf++) {
                    const uint32_t* bp = &bf[nf >> 1][(nf & 1) * 2];
                    const uint32_t* lp = &bfl[nf >> 1][(nf & 1) * 2];
                    mma16(acc[mf][nf], afl[mf], bp);
                    mma16(acc[mf][nf], af[mf],  lp);
                    mma16(acc[mf][nf], af[mf],  bp);
                }
        }
    }

    const int b = bz >> 4, head = bz & 15;
    #pragma unroll
    for (int mf = 0; mf < 2; mf++) {
        #pragma unroll
        for (int nf = 0; nf < 4; nf++) {
            const int gn = wn0 + nf * 8 + 2 * t;
            #pragma unroll
            for (int h = 0; h < 2; h++) {
                const int gm = m0 + wm0 + mf * 16 + g + h * 8;
                float2 p = {acc[mf][nf][h * 2], acc[mf][nf][h * 2 + 1]};
                *(float2*)&ao[((long long)(b * SS + gm)) * DM + head * DK + gn] = p;
            }
        }
    }
}

// ===========================================================================
// Logits GEMM (proven R7): bf16 hi/lo inputs via cp.async. C=(q@k^T)/8 per head.
// ===========================================================================
__global__ void __launch_bounds__(256, 2) gemm_lg(
    const __nv_bfloat16* __restrict__ Qh, const __nv_bfloat16* __restrict__ Ql,
    const __nv_bfloat16* __restrict__ Kh, const __nv_bfloat16* __restrict__ Kl,
    float* __restrict__ C)
{
    constexpr int SK = 72;
    __nv_bfloat16* sm = (__nv_bfloat16*)dynsm;
    __nv_bfloat16* tiles[4] = { sm, sm + 128 * SK, sm + 2 * 128 * SK, sm + 3 * 128 * SK };

    const int bh = blockIdx.z;
    const int tid = threadIdx.x, w = tid >> 5, lane = tid & 31;
    const int g = lane >> 2, t = lane & 3;
    const int m0 = blockIdx.y * 128, n0 = blockIdx.x * 128;
    const int wm0 = (w & 3) * 32, wn0 = (w >> 2) * 64;

    const __nv_bfloat16* srcs[4] = {
        Qh + (long long)bh * SS * DK + (long long)m0 * DK,
        Ql + (long long)bh * SS * DK + (long long)m0 * DK,
        Kh + (long long)bh * SS * DK + (long long)n0 * DK,
        Kl + (long long)bh * SS * DK + (long long)n0 * DK };

    #pragma unroll
    for (int a = 0; a < 4; a++) {
        uint32_t dst = smem_u32(tiles[a]);
        #pragma unroll
        for (int i = 0; i < 4; i++) {
            int idx = tid + i * 256;
            int r = idx >> 3, c = idx & 7;
            cp16(dst + (r * SK + c * 8) * 2, srcs[a] + r * 64 + c * 8);
        }
    }
    asm volatile("cp.async.commit_group;");
    asm volatile("cp.async.wait_group 0;");
    __syncthreads();

    const uint32_t ah_b = smem_u32(tiles[0]), al_b = smem_u32(tiles[1]);
    const uint32_t bh_b = smem_u32(tiles[2]), bl_b = smem_u32(tiles[3]);

    float acc[2][8][4];
    #pragma unroll
    for (int i = 0; i < 2; i++)
        #pragma unroll
        for (int j = 0; j < 8; j++)
            #pragma unroll
            for (int e = 0; e < 4; e++) acc[i][j][e] = 0.f;

    #pragma unroll
    for (int ks = 0; ks < 4; ks++) {
        const int arow = wm0 + (lane & 7) + ((lane >> 3) & 1) * 8;
        const int acol = ks * 16 + (lane >> 4) * 8;
        const int brow = wn0 + (lane & 7) + (lane >> 4) * 8;
        const int bcol = ((lane >> 3) & 1) * 8 + ks * 16;

        uint32_t af[2][4], afl[2][4], bf[4][4], bfl[4][4];
        #pragma unroll
        for (int f = 0; f < 2; f++) {
            uint32_t off = ((arow + f * 16) * SK + acol) * 2;
            ldsm4(af[f],  ah_b + off);
            ldsm4(afl[f], al_b + off);
        }
        #pragma unroll
        for (int p = 0; p < 4; p++) {
            uint32_t off = ((brow + p * 16) * SK + bcol) * 2;
            ldsm4(bf[p],  bh_b + off);
            ldsm4(bfl[p], bl_b + off);
        }

        #pragma unroll
        for (int mf = 0; mf < 2; mf++)
            #pragma unroll
            for (int nf = 0; nf < 8; nf++) {
                const uint32_t* bp = &bf[nf >> 1][(nf & 1) * 2];
                const uint32_t* lp = &bfl[nf >> 1][(nf & 1) * 2];
                mma16(acc[mf][nf], afl[mf], bp);
                mma16(acc[mf][nf], af[mf],  lp);
                mma16(acc[mf][nf], af[mf],  bp);
            }
    }

    float* Cb = C + (long long)bh * SS * SS;
    #pragma unroll
    for (int mf = 0; mf < 2; mf++)
        #pragma unroll
        for (int nf = 0; nf < 8; nf++) {
            const int gn = n0 + wn0 + nf * 8 + 2 * t;
            #pragma unroll
            for (int h = 0; h < 2; h++) {
                const int gm = m0 + wm0 + mf * 16 + g + h * 8;
                float2 p = {acc[mf][nf][h * 2] * 0.125f, acc[mf][nf][h * 2 + 1] * 0.125f};
                *(float2*)&Cb[(long long)gm * SS + gn] = p;
            }
        }
}

// ===========================================================================
// Sparsemax (proven R7): one WARP per row of 2048, in-place, shfl-only.
// ===========================================================================
__global__ void __launch_bounds__(256) sparsemax_kernel(float* __restrict__ attn)
{
    const int row = blockIdx.x * 8 + (threadIdx.x >> 5);
    const int lane = threadIdx.x & 31;
    float* z = attn + (long long)row * SS;

    float4 v[16];
    #pragma unroll
    for (int i = 0; i < 16; i++) v[i] = *(const float4*)(z + i * 128 + lane * 4);

    float mx = -1e30f;
    #pragma unroll
    for (int i = 0; i < 16; i++)
        mx = fmaxf(mx, fmaxf(fmaxf(v[i].x, v[i].y), fmaxf(v[i].z, v[i].w)));
    #pragma unroll
    for (int o = 16; o; o >>= 1) mx = fmaxf(mx, __shfl_xor_sync(0xffffffffu, mx, o));

    float lo = mx - 1.f, hi = mx;
    for (int it = 0; it < 12; it++) {
        float mid = 0.5f * (lo + hi);
        float s = 0.f;
        #pragma unroll
        for (int i = 0; i < 16; i++) {
            s += fmaxf(v[i].x - mid, 0.f) + fmaxf(v[i].y - mid, 0.f);
            s += fmaxf(v[i].z - mid, 0.f) + fmaxf(v[i].w - mid, 0.f);
        }
        #pragma unroll
        for (int o = 16; o; o >>= 1) s += __shfl_xor_sync(0xffffffffu, s, o);
        if (s >= 1.f) lo = mid; else hi = mid;
    }

    float tau = lo;
    for (int it = 0; it < 8; it++) {
        float s = 0.f, c = 0.f;
        #pragma unroll
        for (int i = 0; i < 16; i++) {
            if (v[i].x > tau) { s += v[i].x; c += 1.f; }
            if (v[i].y > tau) { s += v[i].y; c += 1.f; }
            if (v[i].z > tau) { s += v[i].z; c += 1.f; }
            if (v[i].w > tau) { s += v[i].w; c += 1.f; }
        }
        #pragma unroll
        for (int o = 16; o; o >>= 1) {
            s += __shfl_xor_sync(0xffffffffu, s, o);
            c += __shfl_xor_sync(0xffffffffu, c, o);
        }
        float nt = (s - 1.f) / c;   // c >= 1 (row max in support)
        if (nt == tau) break;
        tau = nt;
    }

    #pragma unroll
    for (int i = 0; i < 16; i++) {
        float4 o;
        o.x = fmaxf(v[i].x - tau, 0.f);
        o.y = fmaxf(v[i].y - tau, 0.f);
        o.z = fmaxf(v[i].z - tau, 0.f);
        o.w = fmaxf(v[i].w - tau, 0.f);
        *(float4*)(z + i * 128 + lane * 4) = o;
    }
}

// ---------------------------------------------------------------------------
extern "C" void kernel_launch(void* const* d_in, const int* in_sizes, int n_in,
                              void* d_out, int out_size)
{
    const float* query = (const float*)d_in[0];
    const float* key   = (const float*)d_in[1];
    const float* value = (const float*)d_in[2];
    const float* Wq  = (const float*)d_in[3];  const float* bq  = (const float*)d_in[4];
    const float* Wk  = (const float*)d_in[5];  const float* bk  = (const float*)d_in[6];
    const float* Wv  = (const float*)d_in[7];  const float* bv  = (const float*)d_in[8];
    const float* Wfc = (const float*)d_in[9];  const float* bfc = (const float*)d_in[10];

    float* out  = (float*)d_out;
    float* attn = out + OUT_ELEMS;

    __nv_bfloat16 *pqh, *pql, *pkh, *pkl;
    float *pv, *pao;
    cudaGetSymbolAddress((void**)&pqh, g_qh);
    cudaGetSymbolAddress((void**)&pql, g_ql);
    cudaGetSymbolAddress((void**)&pkh, g_kh);
    cudaGetSymbolAddress((void**)&pkl, g_kl);
    cudaGetSymbolAddress((void**)&pv,  g_v);
    cudaGetSymbolAddress((void**)&pao, g_ao);

    const int LG_SMEM = 4 * 128 * 72 * 2;  // 73728 B
    cudaFuncSetAttribute(gemm_lg, cudaFuncAttributeMaxDynamicSharedMemorySize, LG_SMEM);

    dim3 blk(256);

    // 1) Projections: q,k -> bf16 hi/lo [bh][s][d]; v -> fp32 [bh][d][s]
    gemm_w<1><<<dim3(DM/128, MM/128, 1), blk>>>(query, Wq, bq, nullptr, pqh, pql, DM, DM, 1.f);
    gemm_w<1><<<dim3(DM/128, MM/128, 1), blk>>>(key,   Wk, bk, nullptr, pkh, pkl, DM, DM, 1.f);
    gemm_w<2><<<dim3(DM/128, MM/128, 1), blk>>>(value, Wv, bv, pv, nullptr, nullptr, DM, DM, 1.f);

    // 2) logits = q @ k^T / 8 -> attention slice of d_out
    gemm_lg<<<dim3(SS/128, SS/128, BB*HH), blk, LG_SMEM>>>(pqh, pql, pkh, pkl, attn);

    // 3) sparsemax in place (warp per row)
    sparsemax_kernel<<<BB*HH*SS/8, 256>>>(attn);

    // 4) attn_out = P @ V^T (V stored [bh][d][s]) -> (b,s,h,d) flat
    gemm_pv<<<dim3(1, SS/128, BB*HH), blk>>>(attn, pv, pao);

    // 5) output = attn_out @ Wfc^T + bfc
    gemm_w<0><<<dim3(DM/128, MM/128, 1), blk>>>(pao, Wfc, bfc, out, nullptr, nullptr, DM, DM, 1.f);
}